// round 11
// baseline (speedup 1.0000x reference)
#include <cuda_runtime.h>

// DSA varlen sparse attention, f32.
// q,k,v: (T, H=16, D=64) f32; cu_seqlens: (NDOCS+1) i32;
// topk_indices: (T, 64) i32; topk_scores: (T, 64) f32; out: (T, H, D) f32.
//
// One CTA (256 threads = 8 warps) per token.
//   Phase A: each warp gathers 8 K-rows (4KB each, 8 coalesced float4 passes),
//            computes per-head dots via half-warp shuffle reduction.
//   Phase B: fused softmax * selector-score renorm (denominators cancel).
//   Phase C: each warp gathers its 8 V-rows, accumulates weighted partials in regs.
//   Phase D: cross-warp smem reduction, coalesced float4 store.

#define HH 16
#define DD 64
#define TK 64
#define WARPS 8
#define NTHREADS 256

__global__ __launch_bounds__(NTHREADS) void dsa_sparse_attn_kernel(
    const float* __restrict__ q,
    const float* __restrict__ k,
    const float* __restrict__ v,
    const int*   __restrict__ cu,
    const int*   __restrict__ ti,
    const float* __restrict__ ts,
    float*       __restrict__ out,
    int T, int ndocs)
{
    __shared__ float  q_s[HH * DD];          // 4 KB
    __shared__ float  sc[TK][HH + 1];        // scores -> weights, padded stride 17
    __shared__ float4 part[WARPS][8][32];    // 32 KB per-warp output partials
    __shared__ int    gidx[TK];
    __shared__ float  tsc[TK];

    const int t    = blockIdx.x;
    const int tid  = threadIdx.x;
    const int wid  = tid >> 5;
    const int lane = tid & 31;
    const int half = lane >> 4;   // which head of the pass-pair
    const int sub  = lane & 15;   // position within half-warp

    // ---- load q tile (1024 floats = 256 float4, one per thread) ----
    ((float4*)q_s)[tid] = ((const float4*)(q + (size_t)t * (HH * DD)))[tid];

    // ---- document bounds for this token ----
    int start = 0, stop = T;
    for (int i = 0; i < ndocs; ++i) {
        int a = cu[i], b = cu[i + 1];
        if (t >= a && t < b) { start = a; stop = b; }
    }
    const int len = stop - start;

    // ---- clamp top-k indices into owning doc ----
    if (tid < TK) {
        int loc = ti[(size_t)t * TK + tid] - start;
        loc = loc < 0 ? 0 : (loc > len - 1 ? len - 1 : loc);
        gidx[tid] = start + loc;
        tsc[tid]  = ts[(size_t)t * TK + tid];
    }
    __syncthreads();

    const float scale = 0.125f;  // 64^-0.5

    // ================= Phase A: QK scores =================
    #pragma unroll
    for (int ii = 0; ii < TK / WARPS; ++ii) {
        const int kk = wid * (TK / WARPS) + ii;
        const float4* krow = (const float4*)(k + (size_t)gidx[kk] * (HH * DD));
        float4 kv[8];
        #pragma unroll
        for (int p = 0; p < 8; ++p) kv[p] = krow[p * 32 + lane];  // coalesced 512B/pass
        #pragma unroll
        for (int p = 0; p < 8; ++p) {
            const int h = 2 * p + half;
            const float4 qv = *(const float4*)&q_s[h * DD + sub * 4];
            float s = qv.x * kv[p].x + qv.y * kv[p].y + qv.z * kv[p].z + qv.w * kv[p].w;
            // reduce over the 16 lanes of this half-warp
            s += __shfl_xor_sync(0xffffffffu, s, 1);
            s += __shfl_xor_sync(0xffffffffu, s, 2);
            s += __shfl_xor_sync(0xffffffffu, s, 4);
            s += __shfl_xor_sync(0xffffffffu, s, 8);
            if (sub == 0) sc[kk][h] = s * scale;
        }
    }
    __syncthreads();

    // ========= Phase B: softmax * selector score, renormalized =========
    // w = softmax(s); w *= ts; w /= sum(w)  ==  e^(s-m)*ts / sum(e^(s-m)*ts)
    #pragma unroll
    for (int which = 0; which < 2; ++which) {
        const int h = 2 * wid + which;
        float v0 = sc[lane][h];
        float v1 = sc[lane + 32][h];
        float m = fmaxf(v0, v1);
        #pragma unroll
        for (int o = 16; o; o >>= 1) m = fmaxf(m, __shfl_xor_sync(0xffffffffu, m, o));
        float e0 = __expf(v0 - m) * tsc[lane];
        float e1 = __expf(v1 - m) * tsc[lane + 32];
        float ssum = e0 + e1;
        #pragma unroll
        for (int o = 16; o; o >>= 1) ssum += __shfl_xor_sync(0xffffffffu, ssum, o);
        const float inv = 1.0f / ssum;   // always > 0 (exp > 0, scores in (0,1))
        sc[lane][h]      = e0 * inv;
        sc[lane + 32][h] = e1 * inv;
    }
    __syncthreads();

    // ================= Phase C: weighted V gather =================
    float4 acc[8];
    #pragma unroll
    for (int p = 0; p < 8; ++p) acc[p] = make_float4(0.f, 0.f, 0.f, 0.f);

    #pragma unroll
    for (int ii = 0; ii < TK / WARPS; ++ii) {
        const int kk = wid * (TK / WARPS) + ii;
        const float4* vrow = (const float4*)(v + (size_t)gidx[kk] * (HH * DD));
        float4 vv[8];
        #pragma unroll
        for (int p = 0; p < 8; ++p) vv[p] = vrow[p * 32 + lane];
        #pragma unroll
        for (int p = 0; p < 8; ++p) {
            const float w = sc[kk][2 * p + half];   // half-warp broadcast
            acc[p].x += w * vv[p].x;
            acc[p].y += w * vv[p].y;
            acc[p].z += w * vv[p].z;
            acc[p].w += w * vv[p].w;
        }
    }
    #pragma unroll
    for (int p = 0; p < 8; ++p) part[wid][p][lane] = acc[p];
    __syncthreads();

    // ================= Phase D: cross-warp reduce + store =================
    {
        const int p = wid;   // 8 warps cover the 8 pass-slots
        float4 s = part[0][p][lane];
        #pragma unroll
        for (int w = 1; w < WARPS; ++w) {
            const float4 a = part[w][p][lane];
            s.x += a.x; s.y += a.y; s.z += a.z; s.w += a.w;
        }
        ((float4*)(out + (size_t)t * (HH * DD)))[p * 32 + lane] = s;
    }
}

extern "C" void kernel_launch(void* const* d_in, const int* in_sizes, int n_in,
                              void* d_out, int out_size) {
    const float* q  = (const float*)d_in[0];
    const float* k  = (const float*)d_in[1];
    const float* v  = (const float*)d_in[2];
    const int*   cu = (const int*)d_in[3];
    const int*   ti = (const int*)d_in[4];
    const float* ts = (const float*)d_in[5];
    float* out = (float*)d_out;

    const int T     = in_sizes[0] / (HH * DD);
    const int ndocs = in_sizes[3] - 1;

    dsa_sparse_attn_kernel<<<T, NTHREADS>>>(q, k, v, cu, ti, ts, out, T, ndocs);
}

// round 12
// speedup vs baseline: 1.0040x; 1.0040x over previous
#include <cuda_runtime.h>

// DSA varlen sparse attention, f32.
// q,k,v: (T, H=16, D=64) f32; cu_seqlens: (NDOCS+1) i32;
// topk_indices: (T, 64) i32; topk_scores: (T, 64) f32; out: (T, H, D) f32.
//
// One CTA (256 threads = 8 warps) per token.
//   Phase A: each warp gathers 8 K-rows (4KB each, 8 coalesced float4 passes),
//            computes per-head dots via half-warp shuffle reduction.
//   Phase B: fused softmax * selector-score renorm (denominators cancel).
//   Phase C: each warp gathers its 8 V-rows, accumulates weighted partials in regs.
//   Phase D: cross-warp smem reduction, coalesced float4 store.

#define HH 16
#define DD 64
#define TK 64
#define WARPS 8
#define NTHREADS 256

__global__ __launch_bounds__(NTHREADS) void dsa_sparse_attn_kernel(
    const float* __restrict__ q,
    const float* __restrict__ k,
    const float* __restrict__ v,
    const int*   __restrict__ cu,
    const int*   __restrict__ ti,
    const float* __restrict__ ts,
    float*       __restrict__ out,
    int T, int ndocs)
{
    __shared__ float  q_s[HH * DD];          // 4 KB
    __shared__ float  sc[TK][HH + 1];        // scores -> weights, padded stride 17
    __shared__ float4 part[WARPS][8][32];    // 32 KB per-warp output partials
    __shared__ int    gidx[TK];
    __shared__ float  tsc[TK];

    const int t    = blockIdx.x;
    const int tid  = threadIdx.x;
    const int wid  = tid >> 5;
    const int lane = tid & 31;
    const int half = lane >> 4;   // which head of the pass-pair
    const int sub  = lane & 15;   // position within half-warp

    // ---- load q tile (1024 floats = 256 float4, one per thread) ----
    ((float4*)q_s)[tid] = ((const float4*)(q + (size_t)t * (HH * DD)))[tid];

    // ---- document bounds for this token ----
    int start = 0, stop = T;
    for (int i = 0; i < ndocs; ++i) {
        int a = cu[i], b = cu[i + 1];
        if (t >= a && t < b) { start = a; stop = b; }
    }
    const int len = stop - start;

    // ---- clamp top-k indices into owning doc ----
    if (tid < TK) {
        int loc = ti[(size_t)t * TK + tid] - start;
        loc = loc < 0 ? 0 : (loc > len - 1 ? len - 1 : loc);
        gidx[tid] = start + loc;
        tsc[tid]  = ts[(size_t)t * TK + tid];
    }
    __syncthreads();

    const float scale = 0.125f;  // 64^-0.5

    // ================= Phase A: QK scores =================
    #pragma unroll
    for (int ii = 0; ii < TK / WARPS; ++ii) {
        const int kk = wid * (TK / WARPS) + ii;
        const float4* krow = (const float4*)(k + (size_t)gidx[kk] * (HH * DD));
        float4 kv[8];
        #pragma unroll
        for (int p = 0; p < 8; ++p) kv[p] = krow[p * 32 + lane];  // coalesced 512B/pass
        #pragma unroll
        for (int p = 0; p < 8; ++p) {
            const int h = 2 * p + half;
            const float4 qv = *(const float4*)&q_s[h * DD + sub * 4];
            float s = qv.x * kv[p].x + qv.y * kv[p].y + qv.z * kv[p].z + qv.w * kv[p].w;
            // reduce over the 16 lanes of this half-warp
            s += __shfl_xor_sync(0xffffffffu, s, 1);
            s += __shfl_xor_sync(0xffffffffu, s, 2);
            s += __shfl_xor_sync(0xffffffffu, s, 4);
            s += __shfl_xor_sync(0xffffffffu, s, 8);
            if (sub == 0) sc[kk][h] = s * scale;
        }
    }
    __syncthreads();

    // ========= Phase B: softmax * selector score, renormalized =========
    // w = softmax(s); w *= ts; w /= sum(w)  ==  e^(s-m)*ts / sum(e^(s-m)*ts)
    #pragma unroll
    for (int which = 0; which < 2; ++which) {
        const int h = 2 * wid + which;
        float v0 = sc[lane][h];
        float v1 = sc[lane + 32][h];
        float m = fmaxf(v0, v1);
        #pragma unroll
        for (int o = 16; o; o >>= 1) m = fmaxf(m, __shfl_xor_sync(0xffffffffu, m, o));
        float e0 = __expf(v0 - m) * tsc[lane];
        float e1 = __expf(v1 - m) * tsc[lane + 32];
        float ssum = e0 + e1;
        #pragma unroll
        for (int o = 16; o; o >>= 1) ssum += __shfl_xor_sync(0xffffffffu, ssum, o);
        const float inv = 1.0f / ssum;   // always > 0 (exp > 0, scores in (0,1))
        sc[lane][h]      = e0 * inv;
        sc[lane + 32][h] = e1 * inv;
    }
    __syncthreads();

    // ================= Phase C: weighted V gather =================
    float4 acc[8];
    #pragma unroll
    for (int p = 0; p < 8; ++p) acc[p] = make_float4(0.f, 0.f, 0.f, 0.f);

    #pragma unroll
    for (int ii = 0; ii < TK / WARPS; ++ii) {
        const int kk = wid * (TK / WARPS) + ii;
        const float4* vrow = (const float4*)(v + (size_t)gidx[kk] * (HH * DD));
        float4 vv[8];
        #pragma unroll
        for (int p = 0; p < 8; ++p) vv[p] = vrow[p * 32 + lane];
        #pragma unroll
        for (int p = 0; p < 8; ++p) {
            const float w = sc[kk][2 * p + half];   // half-warp broadcast
            acc[p].x += w * vv[p].x;
            acc[p].y += w * vv[p].y;
            acc[p].z += w * vv[p].z;
            acc[p].w += w * vv[p].w;
        }
    }
    #pragma unroll
    for (int p = 0; p < 8; ++p) part[wid][p][lane] = acc[p];
    __syncthreads();

    // ================= Phase D: cross-warp reduce + store =================
    {
        const int p = wid;   // 8 warps cover the 8 pass-slots
        float4 s = part[0][p][lane];
        #pragma unroll
        for (int w = 1; w < WARPS; ++w) {
            const float4 a = part[w][p][lane];
            s.x += a.x; s.y += a.y; s.z += a.z; s.w += a.w;
        }
        ((float4*)(out + (size_t)t * (HH * DD)))[p * 32 + lane] = s;
    }
}

extern "C" void kernel_launch(void* const* d_in, const int* in_sizes, int n_in,
                              void* d_out, int out_size) {
    const float* q  = (const float*)d_in[0];
    const float* k  = (const float*)d_in[1];
    const float* v  = (const float*)d_in[2];
    const int*   cu = (const int*)d_in[3];
    const int*   ti = (const int*)d_in[4];
    const float* ts = (const float*)d_in[5];
    float* out = (float*)d_out;

    const int T     = in_sizes[0] / (HH * DD);
    const int ndocs = in_sizes[3] - 1;

    dsa_sparse_attn_kernel<<<T, NTHREADS>>>(q, k, v, cu, ti, ts, out, T, ndocs);
}